// round 12
// baseline (speedup 1.0000x reference)
#include <cuda_runtime.h>
#include <cuda_bf16.h>
#include <cuda_fp16.h>
#include <math_constants.h>
#include <cstdint>

// Shapes (fixed by the problem)
#define NB 4
#define TB 8
#define NT (NB*TB)        // 32 batches
#define CC 256            // channels (reduction dim for scores)
#define C2 256            // value channels
#define HW 1024           // p == q == H*W
#define PVAL_ELEMS ((size_t)NT * C2 * HW)
#define KQV_ELEMS (NT * CC * HW)

// ---- scratch (static __device__; no allocation) ----
__device__ __half g_kh[KQV_ELEMS];                      // K fp16
__device__ __half g_qh[KQV_ELEMS];                      // Q fp16
__device__ __half g_vh[KQV_ELEMS];                      // V fp16
__device__ __half g_e[(size_t)NT * HW * HW];            // exp(scores), fp16
__device__ float g_partial[(size_t)NT * 16 * HW];       // per (ptile,mhalf) column sums
__device__ float g_inv[NT * HW];                        // 1 / column sum

// ---------------------------------------------------------------------
// helpers
// ---------------------------------------------------------------------
__device__ __forceinline__ unsigned smaddr(const void* p) {
    return (unsigned)__cvta_generic_to_shared(p);
}
__device__ __forceinline__ void ldsm4(uint32_t* d, unsigned a) {
    asm volatile("ldmatrix.sync.aligned.m8n8.x4.shared.b16 {%0,%1,%2,%3}, [%4];"
                 : "=r"(d[0]), "=r"(d[1]), "=r"(d[2]), "=r"(d[3]) : "r"(a));
}
__device__ __forceinline__ void ldsm4t(uint32_t* d, unsigned a) {
    asm volatile("ldmatrix.sync.aligned.m8n8.x4.trans.shared.b16 {%0,%1,%2,%3}, [%4];"
                 : "=r"(d[0]), "=r"(d[1]), "=r"(d[2]), "=r"(d[3]) : "r"(a));
}
__device__ __forceinline__ void mma16816_f16(float* d, const uint32_t* a, const uint32_t* b) {
    asm volatile("mma.sync.aligned.m16n8k16.row.col.f32.f16.f16.f32 "
                 "{%0,%1,%2,%3}, {%4,%5,%6,%7}, {%8,%9}, {%0,%1,%2,%3};"
                 : "+f"(d[0]), "+f"(d[1]), "+f"(d[2]), "+f"(d[3])
                 : "r"(a[0]), "r"(a[1]), "r"(a[2]), "r"(a[3]), "r"(b[0]), "r"(b[1]));
}
__device__ __forceinline__ void cpasync16(void* dst, const void* src) {
    unsigned d = smaddr(dst);
    asm volatile("cp.async.cg.shared.global [%0], [%1], 16;" :: "r"(d), "l"(src));
}
__device__ __forceinline__ void cp_commit() {
    asm volatile("cp.async.commit_group;");
}
template <int N>
__device__ __forceinline__ void cp_wait() {
    asm volatile("cp.async.wait_group %0;" :: "n"(N));
}

// ---------------------------------------------------------------------
// Kernel 0: splits. y=0: K->fp16; y=1: Q->fp16; y=2: V->fp16
// ---------------------------------------------------------------------
__global__ __launch_bounds__(256) void split_kernel(
    const float* __restrict__ K, const float* __restrict__ Q, const float* __restrict__ V)
{
    int i = blockIdx.x * blockDim.x + threadIdx.x;
    int stride = gridDim.x * blockDim.x;

    const float* src = (blockIdx.y == 0) ? K : (blockIdx.y == 1) ? Q : V;
    __half* dst = (blockIdx.y == 0) ? g_kh : (blockIdx.y == 1) ? g_qh : g_vh;

    for (; i < KQV_ELEMS / 4; i += stride) {
        float4 x = reinterpret_cast<const float4*>(src)[i];
        __half2 hh0 = {__float2half(x.x), __float2half(x.y)};
        __half2 hh1 = {__float2half(x.z), __float2half(x.w)};
        reinterpret_cast<__half2*>(dst)[i * 2 + 0] = hh0;
        reinterpret_cast<__half2*>(dst)[i * 2 + 1] = hh1;
    }
}

// ---------------------------------------------------------------------
// Kernel 1: e[p][q] = exp( (1/16) * sum_c K[c][p]*Q[c][q] )  -> fp16
// Single-product fp16 GEMM. 128 threads, 4 warps, warp tile 64x64,
// BK=32, 3-stage cp.async. fp16 e + fp32 column partial sums out.
// ---------------------------------------------------------------------
struct ScoresStage {
    __half A[32][136], B[32][136];
};

__global__ __launch_bounds__(128, 2) void scores_tc_kernel()
{
    extern __shared__ char dynsmem[];
    ScoresStage* stg = reinterpret_cast<ScoresStage*>(dynsmem);

    const int nt    = blockIdx.z;
    const int pBase = blockIdx.y * 128;
    const int qBase = blockIdx.x * 128;

    const int tid  = threadIdx.x;
    const int lane = tid & 31;
    const int warp = tid >> 5;
    const int wm   = (warp >> 1) * 64;
    const int wn   = (warp & 1) * 64;

    float acc[4][8][4];
    #pragma unroll
    for (int i = 0; i < 4; ++i)
        #pragma unroll
        for (int j = 0; j < 8; ++j)
            #pragma unroll
            for (int k = 0; k < 4; ++k) acc[i][j][k] = 0.f;

    const size_t base = (size_t)nt * CC * HW;

    const int g = lane >> 3, r = lane & 7;
    const int arow  = r + ((g & 2) ? 8 : 0);   // A-trans: k row
    const int acolo = (g & 1) ? 8 : 0;         // A-trans: m col offset
    const int brow  = r + ((g & 1) ? 8 : 0);   // B-trans: k row
    const int bcolo = (g & 2) ? 8 : 0;         // B-trans: n col offset

    auto load_chunk = [&](int buf, int k0) {
        ScoresStage& s = stg[buf];
        #pragma unroll
        for (int j = 0; j < 4; ++j) {
            const int v  = tid + j * 128;     // 0..511
            const int rr = v >> 4;
            const int cc = (v & 15) * 8;
            const size_t ro = base + (size_t)(k0 + rr) * HW;
            cpasync16(&s.A[rr][cc], &g_kh[ro + pBase + cc]);
            cpasync16(&s.B[rr][cc], &g_qh[ro + qBase + cc]);
        }
    };

    const int NCHUNK = CC / 32;   // 8
    load_chunk(0, 0);  cp_commit();
    load_chunk(1, 32); cp_commit();

    #pragma unroll 1
    for (int it = 0; it < NCHUNK; ++it) {
        cp_wait<1>();
        __syncthreads();
        if (it + 2 < NCHUNK) load_chunk((it + 2) % 3, (it + 2) * 32);
        cp_commit();

        ScoresStage& s = stg[it % 3];
        #pragma unroll
        for (int h = 0; h < 2; ++h) {
            uint32_t af[4][4], bf[8][2];
            #pragma unroll
            for (int mt = 0; mt < 4; ++mt)
                ldsm4t(af[mt], smaddr(&s.A[h * 16 + arow][wm + mt * 16 + acolo]));
            #pragma unroll
            for (int np = 0; np < 4; ++np) {
                uint32_t t[4];
                ldsm4t(t, smaddr(&s.B[h * 16 + brow][wn + np * 16 + bcolo]));
                bf[np*2][0] = t[0]; bf[np*2][1] = t[1];
                bf[np*2+1][0] = t[2]; bf[np*2+1][1] = t[3];
            }
            #pragma unroll
            for (int mt = 0; mt < 4; ++mt)
                #pragma unroll
                for (int nn = 0; nn < 8; ++nn)
                    mma16816_f16(acc[mt][nn], af[mt], bf[nn]);
        }
    }

    // epilogue: e = exp(s/16); emit fp16; column partial sums
    const float sc = 1.0f / 16.0f;
    const size_t ebase = (size_t)nt * HW * HW;
    const int tr  = lane >> 2;
    const int tc2 = (lane & 3) * 2;
    float csum[8][2];
    #pragma unroll
    for (int nn = 0; nn < 8; ++nn) { csum[nn][0] = 0.f; csum[nn][1] = 0.f; }

    #pragma unroll
    for (int mt = 0; mt < 4; ++mt) {
        #pragma unroll
        for (int nn = 0; nn < 8; ++nn) {
            const int m = pBase + wm + mt * 16 + tr;
            const int n = qBase + wn + nn * 8 + tc2;
            float e00 = __expf(acc[mt][nn][0] * sc);
            float e01 = __expf(acc[mt][nn][1] * sc);
            float e10 = __expf(acc[mt][nn][2] * sc);
            float e11 = __expf(acc[mt][nn][3] * sc);
            __half2 hh0 = {__float2half(e00), __float2half(e01)};
            __half2 hh1 = {__float2half(e10), __float2half(e11)};
            const size_t o0 = ebase + (size_t)m * HW + n;
            const size_t o1 = o0 + (size_t)8 * HW;
            *(__half2*)&g_e[o0] = hh0;
            *(__half2*)&g_e[o1] = hh1;
            csum[nn][0] += e00 + e10;
            csum[nn][1] += e01 + e11;
        }
    }
    #pragma unroll
    for (int nn = 0; nn < 8; ++nn) {
        #pragma unroll
        for (int j = 0; j < 2; ++j) {
            float v = csum[nn][j];
            v += __shfl_xor_sync(0xFFFFFFFF, v, 4);
            v += __shfl_xor_sync(0xFFFFFFFF, v, 8);
            v += __shfl_xor_sync(0xFFFFFFFF, v, 16);
            csum[nn][j] = v;
        }
    }
    if (lane < 4) {
        const int py2 = blockIdx.y * 2 + (warp >> 1);
        const size_t pb = ((size_t)nt * 16 + py2) * HW;
        #pragma unroll
        for (int nn = 0; nn < 8; ++nn) {
            const int n = qBase + wn + nn * 8 + (lane & 3) * 2;
            g_partial[pb + n]     = csum[nn][0];
            g_partial[pb + n + 1] = csum[nn][1];
        }
    }
}

// ---------------------------------------------------------------------
// Kernel 2: inv[nt][q] = 1 / sum over 16 partials
// ---------------------------------------------------------------------
__global__ __launch_bounds__(256) void inv_kernel()
{
    const int i = blockIdx.x * 256 + threadIdx.x;   // < NT*HW
    const int nt = i >> 10;
    const int q  = i & (HW - 1);
    float s = 0.f;
    #pragma unroll
    for (int j = 0; j < 16; ++j)
        s += g_partial[((size_t)nt * 16 + j) * HW + q];
    g_inv[i] = 1.0f / s;
}

// ---------------------------------------------------------------------
// Kernel 3 (fat): even blocks run pval GEMM CTAs; odd blocks run the
// DRAM-bound normalize, co-scheduled so its traffic hides under MMA work.
//   pval:      p_val[c][q] = inv[q] * sum_p V[c][p] * e[p][q]
//   normalize: attn[p][q]  = e[p][q] * inv[q]
// pval: single-product fp16, 128 threads, warp tile 64x64, BK=16, 4-stage.
// ---------------------------------------------------------------------
struct PvalStage {
    __half V[128][24], T[16][136];
};
#define NORM_BLOCKS 512
#define NORM_THREADS_TOTAL (NORM_BLOCKS * 128)
#define NORM_CHUNKS ((size_t)NT * HW * HW / 8)

__global__ __launch_bounds__(128, 2) void fused_pval_norm_kernel(
    float* __restrict__ O, float* __restrict__ attn)
{
    const int tid = threadIdx.x;

    if (blockIdx.x & 1) {
        // ---------------- normalize path ----------------
        const int nblk = blockIdx.x >> 1;      // 0..511
        for (size_t i = (size_t)nblk * 128 + tid; i < NORM_CHUNKS;
             i += NORM_THREADS_TOTAL) {
            const size_t idx = i * 8;
            const int q  = (int)(idx & (HW - 1));
            const int nt = (int)(idx >> 20);
            float4 iv0 = *(const float4*)&g_inv[nt * HW + q];
            float4 iv1 = *(const float4*)&g_inv[nt * HW + q + 4];
            uint4 ev = *(const uint4*)&g_e[idx];
            const __half2* eh = (const __half2*)&ev;
            float2 a = __half22float2(eh[0]);
            float2 b = __half22float2(eh[1]);
            float2 c = __half22float2(eh[2]);
            float2 d = __half22float2(eh[3]);
            float4 o0, o1;
            o0.x = a.x * iv0.x;  o0.y = a.y * iv0.y;
            o0.z = b.x * iv0.z;  o0.w = b.y * iv0.w;
            o1.x = c.x * iv1.x;  o1.y = c.y * iv1.y;
            o1.z = d.x * iv1.z;  o1.w = d.y * iv1.w;
            *(float4*)&attn[idx]     = o0;
            *(float4*)&attn[idx + 4] = o1;
        }
        return;
    }

    // ---------------- pval GEMM path (R10-proven loop) ----------------
    extern __shared__ char dynsmem[];
    PvalStage* stg = reinterpret_cast<PvalStage*>(dynsmem);
    __shared__ float sinv[128];

    const int pv    = blockIdx.x >> 1;     // 0..511
    const int qi    = pv & 7;
    const int ci    = (pv >> 3) & 1;
    const int nt    = pv >> 4;
    const int cBase = ci * 128;
    const int qBase = qi * 128;

    const int lane = tid & 31;
    const int warp = tid >> 5;
    const int wm   = (warp >> 1) * 64;
    const int wn   = (warp & 1) * 64;

    sinv[tid] = g_inv[nt * HW + qBase + tid];

    float acc[4][8][4];
    #pragma unroll
    for (int i = 0; i < 4; ++i)
        #pragma unroll
        for (int j = 0; j < 8; ++j)
            #pragma unroll
            for (int k = 0; k < 4; ++k) acc[i][j][k] = 0.f;

    const size_t vbase = (size_t)nt * C2 * HW;
    const size_t ebase = (size_t)nt * HW * HW;

    const int g = lane >> 3, r = lane & 7;
    const int amro  = r + ((g & 1) ? 8 : 0);   // A non-trans row offset
    const int acolo = (g & 2) ? 8 : 0;
    const int brow  = r + ((g & 1) ? 8 : 0);   // B-trans
    const int bcolo = (g & 2) ? 8 : 0;

    auto load_chunk = [&](int buf, int k0) {
        PvalStage& s = stg[buf];
        #pragma unroll
        for (int j = 0; j < 2; ++j) {
            const int v  = tid + j * 128;        // 0..255
            const int vr = v >> 1;
            const int vc = (v & 1) * 8;
            const size_t vo = vbase + (size_t)(cBase + vr) * HW + k0 + vc;
            cpasync16(&s.V[vr][vc], &g_vh[vo]);
            const int trr = v >> 4;
            const int tcc = (v & 15) * 8;
            const size_t ao = ebase + (size_t)(k0 + trr) * HW + qBase + tcc;
            cpasync16(&s.T[trr][tcc], &g_e[ao]);
        }
    };

    const int NCHUNK = HW / 16;   // 64
    load_chunk(0, 0);  cp_commit();
    load_chunk(1, 16); cp_commit();
    load_chunk(2, 32); cp_commit();

    #pragma unroll 1
    for (int it = 0; it < NCHUNK; ++it) {
        cp_wait<2>();
        __syncthreads();
        if (it + 3 < NCHUNK) load_chunk((it + 3) & 3, (it + 3) * 16);
        cp_commit();

        PvalStage& s = stg[it & 3];
        uint32_t af[4][4], bf[8][2];

        #pragma unroll
        for (int mt = 0; mt < 4; ++mt)
            ldsm4(af[mt], smaddr(&s.V[wm + mt * 16 + amro][acolo]));
        #pragma unroll
        for (int np = 0; np < 4; ++np) {
            uint32_t t[4];
            ldsm4t(t, smaddr(&s.T[brow][wn + np * 16 + bcolo]));
            bf[np*2][0] = t[0]; bf[np*2][1] = t[1];
            bf[np*2+1][0] = t[2]; bf[np*2+1][1] = t[3];
        }
        #pragma unroll
        for (int mt = 0; mt < 4; ++mt)
            #pragma unroll
            for (int nn = 0; nn < 8; ++nn)
                mma16816_f16(acc[mt][nn], af[mt], bf[nn]);
    }

    float* Ob = O + (size_t)nt * C2 * HW;
    const int tr  = lane >> 2;
    const int tc2 = (lane & 3) * 2;
    #pragma unroll
    for (int mt = 0; mt < 4; ++mt) {
        #pragma unroll
        for (int nn = 0; nn < 8; ++nn) {
            const int m  = cBase + wm + mt * 16 + tr;
            const int nl = wn + nn * 8 + tc2;
            const int n  = qBase + nl;
            const float i0 = sinv[nl], i1 = sinv[nl + 1];
            float2 v0 = {acc[mt][nn][0] * i0, acc[mt][nn][1] * i1};
            float2 v1 = {acc[mt][nn][2] * i0, acc[mt][nn][3] * i1};
            *(float2*)&Ob[(size_t)m * HW + n]       = v0;
            *(float2*)&Ob[(size_t)(m + 8) * HW + n] = v1;
        }
    }
}

// ---------------------------------------------------------------------
extern "C" void kernel_launch(void* const* d_in, const int* in_sizes, int n_in,
                              void* d_out, int out_size)
{
    const float* K = (const float*)d_in[0];
    const float* Q = (const float*)d_in[1];
    const float* V = (const float*)d_in[2];

    float* out  = (float*)d_out;
    float* pval = out;                 // [nt][c2][q]
    float* attn = out + PVAL_ELEMS;    // [nt][p][q]

    const int scores_smem = (int)sizeof(ScoresStage) * 3;   // 52224
    const int pval_smem   = (int)sizeof(PvalStage) * 4;     // 41984
    cudaFuncSetAttribute(scores_tc_kernel,      cudaFuncAttributeMaxDynamicSharedMemorySize, scores_smem);
    cudaFuncSetAttribute(fused_pval_norm_kernel, cudaFuncAttributeMaxDynamicSharedMemorySize, pval_smem);

    // 0) splits: K,Q,V -> fp16
    {
        dim3 grid(512, 3);
        split_kernel<<<grid, 256>>>(K, Q, V);
    }
    // 1) e = exp(scores) fp16 + column partial sums (single-product fp16 GEMM)
    {
        dim3 grid(HW / 128, HW / 128, NT);
        scores_tc_kernel<<<grid, 128, scores_smem>>>();
    }
    // 2) inverse column sums
    inv_kernel<<<(NT * HW) / 256, 256>>>();
    // 3) fat kernel: pval GEMM (even blocks) + attn normalize (odd blocks)
    {
        fused_pval_norm_kernel<<<1024, 128, pval_smem>>>(pval, attn);
    }
}

// round 14
// speedup vs baseline: 1.1328x; 1.1328x over previous
#include <cuda_runtime.h>
#include <cuda_bf16.h>
#include <cuda_fp16.h>
#include <math_constants.h>
#include <cstdint>

// Shapes (fixed by the problem)
#define NB 4
#define TB 8
#define NT (NB*TB)        // 32 batches
#define CC 256            // channels (reduction dim for scores)
#define C2 256            // value channels
#define HW 1024           // p == q == H*W
#define PVAL_ELEMS ((size_t)NT * C2 * HW)
#define KQV_ELEMS (NT * CC * HW)

// ---- scratch (static __device__; no allocation) ----
__device__ __half g_kh[KQV_ELEMS];                      // K fp16
__device__ __half g_qh[KQV_ELEMS];                      // Q fp16
__device__ __half g_vh[KQV_ELEMS];                      // V fp16
__device__ __half g_e[(size_t)NT * HW * HW];            // exp(scores), fp16
__device__ float g_partial[(size_t)NT * 16 * HW];       // per (ptile,mhalf) column sums
__device__ float g_inv[NT * HW];                        // 1 / column sum

// ---------------------------------------------------------------------
// helpers
// ---------------------------------------------------------------------
__device__ __forceinline__ unsigned smaddr(const void* p) {
    return (unsigned)__cvta_generic_to_shared(p);
}
__device__ __forceinline__ void ldsm4(uint32_t* d, unsigned a) {
    asm volatile("ldmatrix.sync.aligned.m8n8.x4.shared.b16 {%0,%1,%2,%3}, [%4];"
                 : "=r"(d[0]), "=r"(d[1]), "=r"(d[2]), "=r"(d[3]) : "r"(a));
}
__device__ __forceinline__ void ldsm4t(uint32_t* d, unsigned a) {
    asm volatile("ldmatrix.sync.aligned.m8n8.x4.trans.shared.b16 {%0,%1,%2,%3}, [%4];"
                 : "=r"(d[0]), "=r"(d[1]), "=r"(d[2]), "=r"(d[3]) : "r"(a));
}
__device__ __forceinline__ void mma16816_f16(float* d, const uint32_t* a, const uint32_t* b) {
    asm volatile("mma.sync.aligned.m16n8k16.row.col.f32.f16.f16.f32 "
                 "{%0,%1,%2,%3}, {%4,%5,%6,%7}, {%8,%9}, {%0,%1,%2,%3};"
                 : "+f"(d[0]), "+f"(d[1]), "+f"(d[2]), "+f"(d[3])
                 : "r"(a[0]), "r"(a[1]), "r"(a[2]), "r"(a[3]), "r"(b[0]), "r"(b[1]));
}
__device__ __forceinline__ void cpasync16(void* dst, const void* src) {
    unsigned d = smaddr(dst);
    asm volatile("cp.async.cg.shared.global [%0], [%1], 16;" :: "r"(d), "l"(src));
}
__device__ __forceinline__ void cp_commit() {
    asm volatile("cp.async.commit_group;");
}
template <int N>
__device__ __forceinline__ void cp_wait() {
    asm volatile("cp.async.wait_group %0;" :: "n"(N));
}
__device__ __forceinline__ void stcs128(void* p, uint4 v) {
    asm volatile("st.global.cs.v4.b32 [%0], {%1,%2,%3,%4};"
                 :: "l"(p), "r"(v.x), "r"(v.y), "r"(v.z), "r"(v.w) : "memory");
}
__device__ __forceinline__ void stcs64(void* p, float2 v) {
    asm volatile("st.global.cs.v2.f32 [%0], {%1,%2};"
                 :: "l"(p), "f"(v.x), "f"(v.y) : "memory");
}

// ---------------------------------------------------------------------
// Kernel 0: splits. y=0: K->fp16; y=1: Q->fp16; y=2: V->fp16
// ---------------------------------------------------------------------
__global__ __launch_bounds__(256) void split_kernel(
    const float* __restrict__ K, const float* __restrict__ Q, const float* __restrict__ V)
{
    int i = blockIdx.x * blockDim.x + threadIdx.x;
    int stride = gridDim.x * blockDim.x;

    const float* src = (blockIdx.y == 0) ? K : (blockIdx.y == 1) ? Q : V;
    __half* dst = (blockIdx.y == 0) ? g_kh : (blockIdx.y == 1) ? g_qh : g_vh;

    for (; i < KQV_ELEMS / 4; i += stride) {
        float4 x = reinterpret_cast<const float4*>(src)[i];
        __half2 hh0 = {__float2half(x.x), __float2half(x.y)};
        __half2 hh1 = {__float2half(x.z), __float2half(x.w)};
        reinterpret_cast<__half2*>(dst)[i * 2 + 0] = hh0;
        reinterpret_cast<__half2*>(dst)[i * 2 + 1] = hh1;
    }
}

// ---------------------------------------------------------------------
// Kernel 1: e[p][q] = exp( (1/16) * sum_c K[c][p]*Q[c][q] )  -> fp16
// Single-product fp16 GEMM. 128 threads, 4 warps, warp tile 64x64,
// BK=32, 3-stage cp.async. Epilogue stages e through smem for
// fully-coalesced 16B stores; fp32 column partial sums out.
// ---------------------------------------------------------------------
struct ScoresStage {
    __half A[32][136], B[32][136];
};

__global__ __launch_bounds__(128, 2) void scores_tc_kernel()
{
    extern __shared__ char dynsmem[];
    ScoresStage* stg = reinterpret_cast<ScoresStage*>(dynsmem);

    const int nt    = blockIdx.z;
    const int pBase = blockIdx.y * 128;
    const int qBase = blockIdx.x * 128;

    const int tid  = threadIdx.x;
    const int lane = tid & 31;
    const int warp = tid >> 5;
    const int wm   = (warp >> 1) * 64;
    const int wn   = (warp & 1) * 64;

    float acc[4][8][4];
    #pragma unroll
    for (int i = 0; i < 4; ++i)
        #pragma unroll
        for (int j = 0; j < 8; ++j)
            #pragma unroll
            for (int k = 0; k < 4; ++k) acc[i][j][k] = 0.f;

    const size_t base = (size_t)nt * CC * HW;

    const int g = lane >> 3, r = lane & 7;
    const int arow  = r + ((g & 2) ? 8 : 0);   // A-trans: k row
    const int acolo = (g & 1) ? 8 : 0;         // A-trans: m col offset
    const int brow  = r + ((g & 1) ? 8 : 0);   // B-trans: k row
    const int bcolo = (g & 2) ? 8 : 0;         // B-trans: n col offset

    auto load_chunk = [&](int buf, int k0) {
        ScoresStage& s = stg[buf];
        #pragma unroll
        for (int j = 0; j < 4; ++j) {
            const int v  = tid + j * 128;     // 0..511
            const int rr = v >> 4;
            const int cc = (v & 15) * 8;
            const size_t ro = base + (size_t)(k0 + rr) * HW;
            cpasync16(&s.A[rr][cc], &g_kh[ro + pBase + cc]);
            cpasync16(&s.B[rr][cc], &g_qh[ro + qBase + cc]);
        }
    };

    const int NCHUNK = CC / 32;   // 8
    load_chunk(0, 0);  cp_commit();
    load_chunk(1, 32); cp_commit();

    #pragma unroll 1
    for (int it = 0; it < NCHUNK; ++it) {
        cp_wait<1>();
        __syncthreads();
        if (it + 2 < NCHUNK) load_chunk((it + 2) % 3, (it + 2) * 32);
        cp_commit();

        ScoresStage& s = stg[it % 3];
        #pragma unroll
        for (int h = 0; h < 2; ++h) {
            uint32_t af[4][4], bf[8][2];
            #pragma unroll
            for (int mt = 0; mt < 4; ++mt)
                ldsm4t(af[mt], smaddr(&s.A[h * 16 + arow][wm + mt * 16 + acolo]));
            #pragma unroll
            for (int np = 0; np < 4; ++np) {
                uint32_t t[4];
                ldsm4t(t, smaddr(&s.B[h * 16 + brow][wn + np * 16 + bcolo]));
                bf[np*2][0] = t[0]; bf[np*2][1] = t[1];
                bf[np*2+1][0] = t[2]; bf[np*2+1][1] = t[3];
            }
            #pragma unroll
            for (int mt = 0; mt < 4; ++mt)
                #pragma unroll
                for (int nn = 0; nn < 8; ++nn)
                    mma16816_f16(acc[mt][nn], af[mt], bf[nn]);
        }
    }

    // ---- epilogue: e = exp(s/16); stage tile in smem; coalesced stores ----
    __half* eT = reinterpret_cast<__half*>(dynsmem);    // [128][136]
    const float sc = 1.0f / 16.0f;
    const size_t ebase = (size_t)nt * HW * HW;
    const int tr  = lane >> 2;
    const int tc2 = (lane & 3) * 2;
    float csum[8][2];
    #pragma unroll
    for (int nn = 0; nn < 8; ++nn) { csum[nn][0] = 0.f; csum[nn][1] = 0.f; }

    __syncthreads();   // all ldsm of stage buffers complete before reuse

    #pragma unroll
    for (int mt = 0; mt < 4; ++mt) {
        #pragma unroll
        for (int nn = 0; nn < 8; ++nn) {
            const int ml = wm + mt * 16 + tr;
            const int nl = wn + nn * 8 + tc2;
            float e00 = __expf(acc[mt][nn][0] * sc);
            float e01 = __expf(acc[mt][nn][1] * sc);
            float e10 = __expf(acc[mt][nn][2] * sc);
            float e11 = __expf(acc[mt][nn][3] * sc);
            *(__half2*)&eT[ml * 136 + nl]       = __half2{__float2half(e00), __float2half(e01)};
            *(__half2*)&eT[(ml + 8) * 136 + nl] = __half2{__float2half(e10), __float2half(e11)};
            csum[nn][0] += e00 + e10;
            csum[nn][1] += e01 + e11;
        }
    }
    #pragma unroll
    for (int nn = 0; nn < 8; ++nn) {
        #pragma unroll
        for (int j = 0; j < 2; ++j) {
            float v = csum[nn][j];
            v += __shfl_xor_sync(0xFFFFFFFF, v, 4);
            v += __shfl_xor_sync(0xFFFFFFFF, v, 8);
            v += __shfl_xor_sync(0xFFFFFFFF, v, 16);
            csum[nn][j] = v;
        }
    }
    if (lane < 4) {
        const int py2 = blockIdx.y * 2 + (warp >> 1);
        const size_t pb = ((size_t)nt * 16 + py2) * HW;
        #pragma unroll
        for (int nn = 0; nn < 8; ++nn) {
            const int n = qBase + wn + nn * 8 + (lane & 3) * 2;
            g_partial[pb + n]     = csum[nn][0];
            g_partial[pb + n + 1] = csum[nn][1];
        }
    }
    __syncthreads();

    // coalesced e stores: 16 x 16B per thread (16 chunks per 128-col row)
    #pragma unroll
    for (int j = 0; j < 16; ++j) {
        const int v   = tid + j * 128;       // 0..2047
        const int row = v >> 4;              // 0..127
        const int c16 = (v & 15) * 8;        // 0..120
        uint4 val = *(uint4*)&eT[row * 136 + c16];
        *(uint4*)&g_e[ebase + (size_t)(pBase + row) * HW + qBase + c16] = val;
    }
}

// ---------------------------------------------------------------------
// Kernel 2: inv[nt][q] = 1 / sum over 16 partials
// ---------------------------------------------------------------------
__global__ __launch_bounds__(256) void inv_kernel()
{
    const int i = blockIdx.x * 256 + threadIdx.x;   // < NT*HW
    const int nt = i >> 10;
    const int q  = i & (HW - 1);
    float s = 0.f;
    #pragma unroll
    for (int j = 0; j < 16; ++j)
        s += g_partial[((size_t)nt * 16 + j) * HW + q];
    g_inv[i] = 1.0f / s;
}

// ---------------------------------------------------------------------
// Kernel 2b: attn[nt][p][q] = e[p][q] * inv[nt][q]   (fp32, evict-first)
// 16 elements per thread: two 16B e loads, four 16B .cs stores.
// ---------------------------------------------------------------------
__global__ __launch_bounds__(256) void normalize_kernel(float* __restrict__ attn)
{
    const size_t i = (size_t)blockIdx.x * 256 + threadIdx.x;
    const size_t idx = i * 16;
    const int q  = (int)(idx & (HW - 1));
    const int nt = (int)(idx >> 20);
    uint4 ev0 = *(const uint4*)&g_e[idx];
    uint4 ev1 = *(const uint4*)&g_e[idx + 8];
    float4 iv0 = *(const float4*)&g_inv[nt * HW + q];
    float4 iv1 = *(const float4*)&g_inv[nt * HW + q + 4];
    float4 iv2 = *(const float4*)&g_inv[nt * HW + q + 8];
    float4 iv3 = *(const float4*)&g_inv[nt * HW + q + 12];
    const __half2* e0 = (const __half2*)&ev0;
    const __half2* e1 = (const __half2*)&ev1;
    float2 a0 = __half22float2(e0[0]), a1 = __half22float2(e0[1]);
    float2 a2 = __half22float2(e0[2]), a3 = __half22float2(e0[3]);
    float2 b0 = __half22float2(e1[0]), b1 = __half22float2(e1[1]);
    float2 b2 = __half22float2(e1[2]), b3 = __half22float2(e1[3]);
    float4 o0 = {a0.x * iv0.x, a0.y * iv0.y, a1.x * iv0.z, a1.y * iv0.w};
    float4 o1 = {a2.x * iv1.x, a2.y * iv1.y, a3.x * iv1.z, a3.y * iv1.w};
    float4 o2 = {b0.x * iv2.x, b0.y * iv2.y, b1.x * iv2.z, b1.y * iv2.w};
    float4 o3 = {b2.x * iv3.x, b2.y * iv3.y, b3.x * iv3.z, b3.y * iv3.w};
    stcs128(&attn[idx],      *(uint4*)&o0);
    stcs128(&attn[idx + 4],  *(uint4*)&o1);
    stcs128(&attn[idx + 8],  *(uint4*)&o2);
    stcs128(&attn[idx + 12], *(uint4*)&o3);
}

// ---------------------------------------------------------------------
// Kernel 3: p_val[c][q] = inv[q] * sum_p V[c][p] * e[p][q]
// Single-product fp16. 128 threads, warp tile 64x64, BK=16, 4-stage.
// Output stores use .cs (never re-read; keep g_e resident in L2).
// ---------------------------------------------------------------------
struct PvalStage {
    __half V[128][24], T[16][136];
};

__global__ __launch_bounds__(128, 2) void pval_tc_kernel(float* __restrict__ O)
{
    extern __shared__ char dynsmem[];
    PvalStage* stg = reinterpret_cast<PvalStage*>(dynsmem);
    __shared__ float sinv[128];

    const int nt    = blockIdx.z;
    const int cBase = blockIdx.y * 128;
    const int qBase = blockIdx.x * 128;

    const int tid  = threadIdx.x;
    const int lane = tid & 31;
    const int warp = tid >> 5;
    const int wm   = (warp >> 1) * 64;
    const int wn   = (warp & 1) * 64;

    sinv[tid] = g_inv[nt * HW + qBase + tid];

    float acc[4][8][4];
    #pragma unroll
    for (int i = 0; i < 4; ++i)
        #pragma unroll
        for (int j = 0; j < 8; ++j)
            #pragma unroll
            for (int k = 0; k < 4; ++k) acc[i][j][k] = 0.f;

    const size_t vbase = (size_t)nt * C2 * HW;
    const size_t ebase = (size_t)nt * HW * HW;

    const int g = lane >> 3, r = lane & 7;
    const int amro  = r + ((g & 1) ? 8 : 0);   // A non-trans row offset
    const int acolo = (g & 2) ? 8 : 0;
    const int brow  = r + ((g & 1) ? 8 : 0);   // B-trans
    const int bcolo = (g & 2) ? 8 : 0;

    auto load_chunk = [&](int buf, int k0) {
        PvalStage& s = stg[buf];
        #pragma unroll
        for (int j = 0; j < 2; ++j) {
            const int v  = tid + j * 128;        // 0..255
            const int vr = v >> 1;
            const int vc = (v & 1) * 8;
            const size_t vo = vbase + (size_t)(cBase + vr) * HW + k0 + vc;
            cpasync16(&s.V[vr][vc], &g_vh[vo]);
            const int trr = v >> 4;
            const int tcc = (v & 15) * 8;
            const size_t ao = ebase + (size_t)(k0 + trr) * HW + qBase + tcc;
            cpasync16(&s.T[trr][tcc], &g_e[ao]);
        }
    };

    const int NCHUNK = HW / 16;   // 64
    load_chunk(0, 0);  cp_commit();
    load_chunk(1, 16); cp_commit();
    load_chunk(2, 32); cp_commit();

    #pragma unroll 1
    for (int it = 0; it < NCHUNK; ++it) {
        cp_wait<2>();
        __syncthreads();
        if (it + 3 < NCHUNK) load_chunk((it + 3) & 3, (it + 3) * 16);
        cp_commit();

        PvalStage& s = stg[it & 3];
        uint32_t af[4][4], bf[8][2];

        #pragma unroll
        for (int mt = 0; mt < 4; ++mt)
            ldsm4(af[mt], smaddr(&s.V[wm + mt * 16 + amro][acolo]));
        #pragma unroll
        for (int np = 0; np < 4; ++np) {
            uint32_t t[4];
            ldsm4t(t, smaddr(&s.T[brow][wn + np * 16 + bcolo]));
            bf[np*2][0] = t[0]; bf[np*2][1] = t[1];
            bf[np*2+1][0] = t[2]; bf[np*2+1][1] = t[3];
        }
        #pragma unroll
        for (int mt = 0; mt < 4; ++mt)
            #pragma unroll
            for (int nn = 0; nn < 8; ++nn)
                mma16816_f16(acc[mt][nn], af[mt], bf[nn]);
    }

    float* Ob = O + (size_t)nt * C2 * HW;
    const int tr  = lane >> 2;
    const int tc2 = (lane & 3) * 2;
    #pragma unroll
    for (int mt = 0; mt < 4; ++mt) {
        #pragma unroll
        for (int nn = 0; nn < 8; ++nn) {
            const int m  = cBase + wm + mt * 16 + tr;
            const int nl = wn + nn * 8 + tc2;
            const int n  = qBase + nl;
            const float i0 = sinv[nl], i1 = sinv[nl + 1];
            float2 v0 = {acc[mt][nn][0] * i0, acc[mt][nn][1] * i1};
            float2 v1 = {acc[mt][nn][2] * i0, acc[mt][nn][3] * i1};
            stcs64(&Ob[(size_t)m * HW + n],       v0);
            stcs64(&Ob[(size_t)(m + 8) * HW + n], v1);
        }
    }
}

// ---------------------------------------------------------------------
extern "C" void kernel_launch(void* const* d_in, const int* in_sizes, int n_in,
                              void* d_out, int out_size)
{
    const float* K = (const float*)d_in[0];
    const float* Q = (const float*)d_in[1];
    const float* V = (const float*)d_in[2];

    float* out  = (float*)d_out;
    float* pval = out;                 // [nt][c2][q]
    float* attn = out + PVAL_ELEMS;    // [nt][p][q]

    const int scores_smem = (int)sizeof(ScoresStage) * 3;   // 52224 (>= 128*136*2)
    const int pval_smem   = (int)sizeof(PvalStage) * 4;     // 41984
    cudaFuncSetAttribute(scores_tc_kernel, cudaFuncAttributeMaxDynamicSharedMemorySize, scores_smem);
    cudaFuncSetAttribute(pval_tc_kernel,   cudaFuncAttributeMaxDynamicSharedMemorySize, pval_smem);

    // 0) splits: K,Q,V -> fp16
    {
        dim3 grid(512, 3);
        split_kernel<<<grid, 256>>>(K, Q, V);
    }
    // 1) e = exp(scores) fp16 + column partial sums (single-product fp16 GEMM)
    {
        dim3 grid(HW / 128, HW / 128, NT);
        scores_tc_kernel<<<grid, 128, scores_smem>>>();
    }
    // 2) inverse column sums
    inv_kernel<<<(NT * HW) / 256, 256>>>();
    // 2b) attn = e * inv (evict-first stores)
    {
        const size_t nchunk = (size_t)NT * HW * HW / 16;
        normalize_kernel<<<(unsigned)(nchunk / 256), 256>>>(attn);
    }
    // 3) p_val = (V @ e) * inv
    {
        dim3 grid(HW / 128, C2 / 128, NT);
        pval_tc_kernel<<<grid, 128, pval_smem>>>(pval);
    }
}

// round 15
// speedup vs baseline: 1.2100x; 1.0682x over previous
#include <cuda_runtime.h>
#include <cuda_bf16.h>
#include <cuda_fp16.h>
#include <math_constants.h>
#include <cstdint>

// Shapes (fixed by the problem)
#define NB 4
#define TB 8
#define NT (NB*TB)        // 32 batches
#define CC 256            // channels (reduction dim for scores)
#define C2 256            // value channels
#define HW 1024           // p == q == H*W
#define PVAL_ELEMS ((size_t)NT * C2 * HW)
#define KQV_ELEMS (NT * CC * HW)

// ---- scratch (static __device__; no allocation) ----
__device__ __half g_kh[KQV_ELEMS];                      // K fp16
__device__ __half g_qh[KQV_ELEMS];                      // Q fp16
__device__ __half g_vh[KQV_ELEMS];                      // V fp16
__device__ __half g_e[(size_t)NT * HW * HW];            // exp(scores), fp16
__device__ float g_partial[(size_t)NT * 16 * HW];       // per (ptile,mhalf) column sums
__device__ float g_inv[NT * HW];                        // 1 / column sum

// ---------------------------------------------------------------------
// helpers
// ---------------------------------------------------------------------
__device__ __forceinline__ unsigned smaddr(const void* p) {
    return (unsigned)__cvta_generic_to_shared(p);
}
__device__ __forceinline__ void ldsm4(uint32_t* d, unsigned a) {
    asm volatile("ldmatrix.sync.aligned.m8n8.x4.shared.b16 {%0,%1,%2,%3}, [%4];"
                 : "=r"(d[0]), "=r"(d[1]), "=r"(d[2]), "=r"(d[3]) : "r"(a));
}
__device__ __forceinline__ void ldsm4t(uint32_t* d, unsigned a) {
    asm volatile("ldmatrix.sync.aligned.m8n8.x4.trans.shared.b16 {%0,%1,%2,%3}, [%4];"
                 : "=r"(d[0]), "=r"(d[1]), "=r"(d[2]), "=r"(d[3]) : "r"(a));
}
__device__ __forceinline__ void mma16816_f16(float* d, const uint32_t* a, const uint32_t* b) {
    asm volatile("mma.sync.aligned.m16n8k16.row.col.f32.f16.f16.f32 "
                 "{%0,%1,%2,%3}, {%4,%5,%6,%7}, {%8,%9}, {%0,%1,%2,%3};"
                 : "+f"(d[0]), "+f"(d[1]), "+f"(d[2]), "+f"(d[3])
                 : "r"(a[0]), "r"(a[1]), "r"(a[2]), "r"(a[3]), "r"(b[0]), "r"(b[1]));
}
__device__ __forceinline__ void cpasync16(void* dst, const void* src) {
    unsigned d = smaddr(dst);
    asm volatile("cp.async.cg.shared.global [%0], [%1], 16;" :: "r"(d), "l"(src));
}
__device__ __forceinline__ void cp_commit() {
    asm volatile("cp.async.commit_group;");
}
template <int N>
__device__ __forceinline__ void cp_wait() {
    asm volatile("cp.async.wait_group %0;" :: "n"(N));
}
__device__ __forceinline__ void stcs64(void* p, float2 v) {
    asm volatile("st.global.cs.v2.f32 [%0], {%1,%2};"
                 :: "l"(p), "f"(v.x), "f"(v.y) : "memory");
}

// ---------------------------------------------------------------------
// Kernel 0: splits. y=0: K->fp16; y=1: Q->fp16; y=2: V->fp16
// ---------------------------------------------------------------------
__global__ __launch_bounds__(256) void split_kernel(
    const float* __restrict__ K, const float* __restrict__ Q, const float* __restrict__ V)
{
    int i = blockIdx.x * blockDim.x + threadIdx.x;
    int stride = gridDim.x * blockDim.x;

    const float* src = (blockIdx.y == 0) ? K : (blockIdx.y == 1) ? Q : V;
    __half* dst = (blockIdx.y == 0) ? g_kh : (blockIdx.y == 1) ? g_qh : g_vh;

    for (; i < KQV_ELEMS / 4; i += stride) {
        float4 x = reinterpret_cast<const float4*>(src)[i];
        __half2 hh0 = {__float2half(x.x), __float2half(x.y)};
        __half2 hh1 = {__float2half(x.z), __float2half(x.w)};
        reinterpret_cast<__half2*>(dst)[i * 2 + 0] = hh0;
        reinterpret_cast<__half2*>(dst)[i * 2 + 1] = hh1;
    }
}

// ---------------------------------------------------------------------
// Kernel 1: e[p][q] = exp( (1/16) * sum_c K[c][p]*Q[c][q] )  -> fp16
// Single-product fp16 GEMM. 128 threads, 4 warps, warp tile 64x64,
// BK=32, 3-stage cp.async. Epilogue stages e through smem for
// fully-coalesced 16B stores; fp32 column partial sums out.
// ---------------------------------------------------------------------
struct ScoresStage {
    __half A[32][136], B[32][136];
};

__global__ __launch_bounds__(128, 2) void scores_tc_kernel()
{
    extern __shared__ char dynsmem[];
    ScoresStage* stg = reinterpret_cast<ScoresStage*>(dynsmem);

    const int nt    = blockIdx.z;
    const int pBase = blockIdx.y * 128;
    const int qBase = blockIdx.x * 128;

    const int tid  = threadIdx.x;
    const int lane = tid & 31;
    const int warp = tid >> 5;
    const int wm   = (warp >> 1) * 64;
    const int wn   = (warp & 1) * 64;

    float acc[4][8][4];
    #pragma unroll
    for (int i = 0; i < 4; ++i)
        #pragma unroll
        for (int j = 0; j < 8; ++j)
            #pragma unroll
            for (int k = 0; k < 4; ++k) acc[i][j][k] = 0.f;

    const size_t base = (size_t)nt * CC * HW;

    const int g = lane >> 3, r = lane & 7;
    const int arow  = r + ((g & 2) ? 8 : 0);   // A-trans: k row
    const int acolo = (g & 1) ? 8 : 0;         // A-trans: m col offset
    const int brow  = r + ((g & 1) ? 8 : 0);   // B-trans: k row
    const int bcolo = (g & 2) ? 8 : 0;         // B-trans: n col offset

    auto load_chunk = [&](int buf, int k0) {
        ScoresStage& s = stg[buf];
        #pragma unroll
        for (int j = 0; j < 4; ++j) {
            const int v  = tid + j * 128;     // 0..511
            const int rr = v >> 4;
            const int cc = (v & 15) * 8;
            const size_t ro = base + (size_t)(k0 + rr) * HW;
            cpasync16(&s.A[rr][cc], &g_kh[ro + pBase + cc]);
            cpasync16(&s.B[rr][cc], &g_qh[ro + qBase + cc]);
        }
    };

    const int NCHUNK = CC / 32;   // 8
    load_chunk(0, 0);  cp_commit();
    load_chunk(1, 32); cp_commit();

    #pragma unroll 1
    for (int it = 0; it < NCHUNK; ++it) {
        cp_wait<1>();
        __syncthreads();
        if (it + 2 < NCHUNK) load_chunk((it + 2) % 3, (it + 2) * 32);
        cp_commit();

        ScoresStage& s = stg[it % 3];
        #pragma unroll
        for (int h = 0; h < 2; ++h) {
            uint32_t af[4][4], bf[8][2];
            #pragma unroll
            for (int mt = 0; mt < 4; ++mt)
                ldsm4t(af[mt], smaddr(&s.A[h * 16 + arow][wm + mt * 16 + acolo]));
            #pragma unroll
            for (int np = 0; np < 4; ++np) {
                uint32_t t[4];
                ldsm4t(t, smaddr(&s.B[h * 16 + brow][wn + np * 16 + bcolo]));
                bf[np*2][0] = t[0]; bf[np*2][1] = t[1];
                bf[np*2+1][0] = t[2]; bf[np*2+1][1] = t[3];
            }
            #pragma unroll
            for (int mt = 0; mt < 4; ++mt)
                #pragma unroll
                for (int nn = 0; nn < 8; ++nn)
                    mma16816_f16(acc[mt][nn], af[mt], bf[nn]);
        }
    }

    // ---- epilogue: e = exp(s/16); stage tile in smem; coalesced stores ----
    __half* eT = reinterpret_cast<__half*>(dynsmem);    // [128][136]
    const float sc = 1.0f / 16.0f;
    const size_t ebase = (size_t)nt * HW * HW;
    const int tr  = lane >> 2;
    const int tc2 = (lane & 3) * 2;
    float csum[8][2];
    #pragma unroll
    for (int nn = 0; nn < 8; ++nn) { csum[nn][0] = 0.f; csum[nn][1] = 0.f; }

    __syncthreads();   // all ldsm of stage buffers complete before reuse

    #pragma unroll
    for (int mt = 0; mt < 4; ++mt) {
        #pragma unroll
        for (int nn = 0; nn < 8; ++nn) {
            const int ml = wm + mt * 16 + tr;
            const int nl = wn + nn * 8 + tc2;
            float e00 = __expf(acc[mt][nn][0] * sc);
            float e01 = __expf(acc[mt][nn][1] * sc);
            float e10 = __expf(acc[mt][nn][2] * sc);
            float e11 = __expf(acc[mt][nn][3] * sc);
            *(__half2*)&eT[ml * 136 + nl]       = __half2{__float2half(e00), __float2half(e01)};
            *(__half2*)&eT[(ml + 8) * 136 + nl] = __half2{__float2half(e10), __float2half(e11)};
            csum[nn][0] += e00 + e10;
            csum[nn][1] += e01 + e11;
        }
    }
    #pragma unroll
    for (int nn = 0; nn < 8; ++nn) {
        #pragma unroll
        for (int j = 0; j < 2; ++j) {
            float v = csum[nn][j];
            v += __shfl_xor_sync(0xFFFFFFFF, v, 4);
            v += __shfl_xor_sync(0xFFFFFFFF, v, 8);
            v += __shfl_xor_sync(0xFFFFFFFF, v, 16);
            csum[nn][j] = v;
        }
    }
    if (lane < 4) {
        const int py2 = blockIdx.y * 2 + (warp >> 1);
        const size_t pb = ((size_t)nt * 16 + py2) * HW;
        #pragma unroll
        for (int nn = 0; nn < 8; ++nn) {
            const int n = qBase + wn + nn * 8 + (lane & 3) * 2;
            g_partial[pb + n]     = csum[nn][0];
            g_partial[pb + n + 1] = csum[nn][1];
        }
    }
    __syncthreads();

    // coalesced e stores: 16 x 16B per thread (16 chunks per 128-col row)
    #pragma unroll
    for (int j = 0; j < 16; ++j) {
        const int v   = tid + j * 128;       // 0..2047
        const int row = v >> 4;              // 0..127
        const int c16 = (v & 15) * 8;        // 0..120
        uint4 val = *(uint4*)&eT[row * 136 + c16];
        *(uint4*)&g_e[ebase + (size_t)(pBase + row) * HW + qBase + c16] = val;
    }
}

// ---------------------------------------------------------------------
// Kernel 2: inv[nt][q] = 1 / sum over 16 partials
// ---------------------------------------------------------------------
__global__ __launch_bounds__(256) void inv_kernel()
{
    const int i = blockIdx.x * 256 + threadIdx.x;   // < NT*HW
    const int nt = i >> 10;
    const int q  = i & (HW - 1);
    float s = 0.f;
    #pragma unroll
    for (int j = 0; j < 16; ++j)
        s += g_partial[((size_t)nt * 16 + j) * HW + q];
    g_inv[i] = 1.0f / s;
}

// ---------------------------------------------------------------------
// Kernel 2b: attn[nt][p][q] = e[p][q] * inv[nt][q]   (fp32 output)
// 8 elements per thread: 16B e load, two 16B stores. (R10-proven)
// ---------------------------------------------------------------------
__global__ __launch_bounds__(256) void normalize_kernel(float* __restrict__ attn)
{
    const size_t i = (size_t)blockIdx.x * 256 + threadIdx.x;  // one 8-elem chunk
    const size_t idx = i * 8;
    const int q  = (int)(idx & (HW - 1));
    const int nt = (int)(idx >> 20);
    float4 iv0 = *(const float4*)&g_inv[nt * HW + q];
    float4 iv1 = *(const float4*)&g_inv[nt * HW + q + 4];
    uint4 ev = *(const uint4*)&g_e[idx];
    const __half2* eh = (const __half2*)&ev;
    float2 a = __half22float2(eh[0]);
    float2 b = __half22float2(eh[1]);
    float2 c = __half22float2(eh[2]);
    float2 d = __half22float2(eh[3]);
    float4 o0, o1;
    o0.x = a.x * iv0.x;  o0.y = a.y * iv0.y;
    o0.z = b.x * iv0.z;  o0.w = b.y * iv0.w;
    o1.x = c.x * iv1.x;  o1.y = c.y * iv1.y;
    o1.z = d.x * iv1.z;  o1.w = d.y * iv1.w;
    *(float4*)&attn[idx]     = o0;
    *(float4*)&attn[idx + 4] = o1;
}

// ---------------------------------------------------------------------
// Kernel 3: p_val[c][q] = inv[q] * sum_p V[c][p] * e[p][q]
// Single-product fp16. 128 threads, warp tile 64x64, BK=16, 4-stage.
// Output stores use .cs (never re-read; keep g_e resident in L2).
// ---------------------------------------------------------------------
struct PvalStage {
    __half V[128][24], T[16][136];
};

__global__ __launch_bounds__(128, 2) void pval_tc_kernel(float* __restrict__ O)
{
    extern __shared__ char dynsmem[];
    PvalStage* stg = reinterpret_cast<PvalStage*>(dynsmem);
    __shared__ float sinv[128];

    const int nt    = blockIdx.z;
    const int cBase = blockIdx.y * 128;
    const int qBase = blockIdx.x * 128;

    const int tid  = threadIdx.x;
    const int lane = tid & 31;
    const int warp = tid >> 5;
    const int wm   = (warp >> 1) * 64;
    const int wn   = (warp & 1) * 64;

    sinv[tid] = g_inv[nt * HW + qBase + tid];

    float acc[4][8][4];
    #pragma unroll
    for (int i = 0; i < 4; ++i)
        #pragma unroll
        for (int j = 0; j < 8; ++j)
            #pragma unroll
            for (int k = 0; k < 4; ++k) acc[i][j][k] = 0.f;

    const size_t vbase = (size_t)nt * C2 * HW;
    const size_t ebase = (size_t)nt * HW * HW;

    const int g = lane >> 3, r = lane & 7;
    const int amro  = r + ((g & 1) ? 8 : 0);   // A non-trans row offset
    const int acolo = (g & 2) ? 8 : 0;
    const int brow  = r + ((g & 1) ? 8 : 0);   // B-trans
    const int bcolo = (g & 2) ? 8 : 0;

    auto load_chunk = [&](int buf, int k0) {
        PvalStage& s = stg[buf];
        #pragma unroll
        for (int j = 0; j < 2; ++j) {
            const int v  = tid + j * 128;        // 0..255
            const int vr = v >> 1;
            const int vc = (v & 1) * 8;
            const size_t vo = vbase + (size_t)(cBase + vr) * HW + k0 + vc;
            cpasync16(&s.V[vr][vc], &g_vh[vo]);
            const int trr = v >> 4;
            const int tcc = (v & 15) * 8;
            const size_t ao = ebase + (size_t)(k0 + trr) * HW + qBase + tcc;
            cpasync16(&s.T[trr][tcc], &g_e[ao]);
        }
    };

    const int NCHUNK = HW / 16;   // 64
    load_chunk(0, 0);  cp_commit();
    load_chunk(1, 16); cp_commit();
    load_chunk(2, 32); cp_commit();

    #pragma unroll 1
    for (int it = 0; it < NCHUNK; ++it) {
        cp_wait<2>();
        __syncthreads();
        if (it + 3 < NCHUNK) load_chunk((it + 3) & 3, (it + 3) * 16);
        cp_commit();

        PvalStage& s = stg[it & 3];
        uint32_t af[4][4], bf[8][2];

        #pragma unroll
        for (int mt = 0; mt < 4; ++mt)
            ldsm4(af[mt], smaddr(&s.V[wm + mt * 16 + amro][acolo]));
        #pragma unroll
        for (int np = 0; np < 4; ++np) {
            uint32_t t[4];
            ldsm4t(t, smaddr(&s.T[brow][wn + np * 16 + bcolo]));
            bf[np*2][0] = t[0]; bf[np*2][1] = t[1];
            bf[np*2+1][0] = t[2]; bf[np*2+1][1] = t[3];
        }
        #pragma unroll
        for (int mt = 0; mt < 4; ++mt)
            #pragma unroll
            for (int nn = 0; nn < 8; ++nn)
                mma16816_f16(acc[mt][nn], af[mt], bf[nn]);
    }

    float* Ob = O + (size_t)nt * C2 * HW;
    const int tr  = lane >> 2;
    const int tc2 = (lane & 3) * 2;
    #pragma unroll
    for (int mt = 0; mt < 4; ++mt) {
        #pragma unroll
        for (int nn = 0; nn < 8; ++nn) {
            const int m  = cBase + wm + mt * 16 + tr;
            const int nl = wn + nn * 8 + tc2;
            const int n  = qBase + nl;
            const float i0 = sinv[nl], i1 = sinv[nl + 1];
            float2 v0 = {acc[mt][nn][0] * i0, acc[mt][nn][1] * i1};
            float2 v1 = {acc[mt][nn][2] * i0, acc[mt][nn][3] * i1};
            stcs64(&Ob[(size_t)m * HW + n],       v0);
            stcs64(&Ob[(size_t)(m + 8) * HW + n], v1);
        }
    }
}

// ---------------------------------------------------------------------
extern "C" void kernel_launch(void* const* d_in, const int* in_sizes, int n_in,
                              void* d_out, int out_size)
{
    const float* K = (const float*)d_in[0];
    const float* Q = (const float*)d_in[1];
    const float* V = (const float*)d_in[2];

    float* out  = (float*)d_out;
    float* pval = out;                 // [nt][c2][q]
    float* attn = out + PVAL_ELEMS;    // [nt][p][q]

    const int scores_smem = (int)sizeof(ScoresStage) * 3;   // 52224 (>= 128*136*2)
    const int pval_smem   = (int)sizeof(PvalStage) * 4;     // 41984
    cudaFuncSetAttribute(scores_tc_kernel, cudaFuncAttributeMaxDynamicSharedMemorySize, scores_smem);
    cudaFuncSetAttribute(pval_tc_kernel,   cudaFuncAttributeMaxDynamicSharedMemorySize, pval_smem);

    // 0) splits: K,Q,V -> fp16
    {
        dim3 grid(512, 3);
        split_kernel<<<grid, 256>>>(K, Q, V);
    }
    // 1) e = exp(scores) fp16 + column partial sums (single-product fp16 GEMM)
    {
        dim3 grid(HW / 128, HW / 128, NT);
        scores_tc_kernel<<<grid, 128, scores_smem>>>();
    }
    // 2) inverse column sums
    inv_kernel<<<(NT * HW) / 256, 256>>>();
    // 2b) attn = e * inv
    {
        const size_t nchunk = (size_t)NT * HW * HW / 8;
        normalize_kernel<<<(unsigned)(nchunk / 256), 256>>>(attn);
    }
    // 3) p_val = (V @ e) * inv
    {
        dim3 grid(HW / 128, C2 / 128, NT);
        pval_tc_kernel<<<grid, 128, pval_smem>>>(pval);
    }
}